// round 1
// baseline (speedup 1.0000x reference)
#include <cuda_runtime.h>
#include <math.h>

// Problem constants
#define Bv   8
#define Mv   256
#define Ev   128
#define Kv   16
#define Hv   1024
#define Av   256
#define Rv   1024
#define RMSv 512
#define NEGV (-1e25f)

#define MROWS (Bv*Ev*Kv)   // 16384 gathered mention rows
#define NBE   (Bv*Ev)      // 1024 entities total

// -------- scratch (static device globals; no allocations allowed) --------
__device__ float g_logits[MROWS];          // 64 KB
__device__ float g_er[NBE * Hv];           // 4 MB   entity_reprs
__device__ float g_sw[Rv * Hv];            // 4 MB   s_w
__device__ float g_s [NBE * Rv];           // 4 MB   s
__device__ float g_s2[NBE * RMSv];         // 2 MB   s @ relation_memory

// ---------------------------------------------------------------------------
__global__ void zero_logits_kernel() {
    int i = blockIdx.x * blockDim.x + threadIdx.x;
    if (i < MROWS) g_logits[i] = 0.0f;
}

// ---------------------------------------------------------------------------
// Fused gather + (X@Wv^T) + (X@Wu^T) + tanh*sigmoid*Wa epilogue -> logits
// X row m = mention_reprs[b, entities[m], :],  b = m / (E*K)
// Tiles: BM=64, BN=64, BK=16, 256 threads, 4x4 microtile (dual accumulators)
// ---------------------------------------------------------------------------
__global__ __launch_bounds__(256)
void gated_mil_kernel(const float* __restrict__ mention,
                      const int*   __restrict__ entities,
                      const float* __restrict__ Wv, const float* __restrict__ bv,
                      const float* __restrict__ Wu, const float* __restrict__ bu,
                      const float* __restrict__ Wa)
{
    const int BM = 64, BN = 64, BK = 16;
    __shared__ __align__(16) float As [BK][BM];
    __shared__ __align__(16) float Bvs[BK][BN];
    __shared__ __align__(16) float Bus[BK][BN];
    __shared__ float red[64][16];

    const int tid = threadIdx.x;
    const int tx  = tid & 15;
    const int ty  = tid >> 4;
    const int m0  = blockIdx.y * BM;
    const int n0  = blockIdx.x * BN;

    // load assignment: each thread loads one float4 per tile per operand
    const int lrow = tid >> 2;          // 0..63
    const int lc4  = (tid & 3) * 4;     // 0,4,8,12

    const int gm   = m0 + lrow;
    const int bidx = gm >> 11;          // / (E*K) = /2048
    const int arow = bidx * Mv + entities[gm];
    const float* aptr  = mention + (size_t)arow * Hv;
    const float* bvptr = Wv + (size_t)(n0 + lrow) * Hv;
    const float* buptr = Wu + (size_t)(n0 + lrow) * Hv;

    float accV[4][4] = {};
    float accU[4][4] = {};

    for (int k0 = 0; k0 < Hv; k0 += BK) {
        float4 a4 = *(const float4*)(aptr  + k0 + lc4);
        float4 v4 = *(const float4*)(bvptr + k0 + lc4);
        float4 u4 = *(const float4*)(buptr + k0 + lc4);
        As [lc4+0][lrow] = a4.x; As [lc4+1][lrow] = a4.y;
        As [lc4+2][lrow] = a4.z; As [lc4+3][lrow] = a4.w;
        Bvs[lc4+0][lrow] = v4.x; Bvs[lc4+1][lrow] = v4.y;
        Bvs[lc4+2][lrow] = v4.z; Bvs[lc4+3][lrow] = v4.w;
        Bus[lc4+0][lrow] = u4.x; Bus[lc4+1][lrow] = u4.y;
        Bus[lc4+2][lrow] = u4.z; Bus[lc4+3][lrow] = u4.w;
        __syncthreads();
        #pragma unroll
        for (int k = 0; k < BK; k++) {
            float4 a  = *(const float4*)&As [k][ty*4];
            float4 bV = *(const float4*)&Bvs[k][tx*4];
            float4 bU = *(const float4*)&Bus[k][tx*4];
            float ar[4] = {a.x, a.y, a.z, a.w};
            float vr[4] = {bV.x, bV.y, bV.z, bV.w};
            float ur[4] = {bU.x, bU.y, bU.z, bU.w};
            #pragma unroll
            for (int i = 0; i < 4; i++)
                #pragma unroll
                for (int j = 0; j < 4; j++) {
                    accV[i][j] += ar[i] * vr[j];
                    accU[i][j] += ar[i] * ur[j];
                }
        }
        __syncthreads();
    }

    // epilogue: g = tanh(v+bv)*sigmoid(u+bu); partial logit = sum_a g*Wa[a]
    #pragma unroll
    for (int i = 0; i < 4; i++) {
        float s = 0.0f;
        #pragma unroll
        for (int j = 0; j < 4; j++) {
            int ai = n0 + tx*4 + j;
            float tv = tanhf(accV[i][j] + bv[ai]);
            float su = 1.0f / (1.0f + expf(-(accU[i][j] + bu[ai])));
            s += tv * su * Wa[ai];
        }
        red[ty*4 + i][tx] = s;
    }
    __syncthreads();
    if (tid < 64) {
        float t = 0.0f;
        #pragma unroll
        for (int x = 0; x < 16; x++) t += red[tid][x];
        atomicAdd(&g_logits[m0 + tid], t);
    }
}

// ---------------------------------------------------------------------------
// softmax over K (masked) + weighted pooling of gathered mention rows
// one block per (b,e)
// ---------------------------------------------------------------------------
__global__ __launch_bounds__(256)
void softmax_pool_kernel(const float* __restrict__ mention,
                         const int*   __restrict__ entities,
                         const int*   __restrict__ masks)
{
    const int be = blockIdx.x;
    const int b  = be / Ev;
    __shared__ float w[Kv];
    __shared__ int   idx[Kv];

    const int tid = threadIdx.x;
    if (tid < Kv) {
        int r = be * Kv + tid;
        idx[tid] = entities[r];
        w[tid]   = masks[r] ? g_logits[r] : NEGV;
    }
    __syncthreads();
    if (tid == 0) {
        float mx = w[0];
        #pragma unroll
        for (int k = 1; k < Kv; k++) mx = fmaxf(mx, w[k]);
        float s = 0.0f;
        #pragma unroll
        for (int k = 0; k < Kv; k++) { float e = expf(w[k] - mx); w[k] = e; s += e; }
        float inv = 1.0f / s;
        #pragma unroll
        for (int k = 0; k < Kv; k++) w[k] *= inv;
    }
    __syncthreads();

    float ww[Kv]; int ii[Kv];
    #pragma unroll
    for (int k = 0; k < Kv; k++) { ww[k] = w[k]; ii[k] = idx[k]; }

    const float* base = mention + (size_t)b * Mv * Hv;
    for (int h = tid; h < Hv; h += 256) {
        float acc = 0.0f;
        #pragma unroll
        for (int k = 0; k < Kv; k++)
            acc += ww[k] * base[(size_t)ii[k] * Hv + h];
        g_er[(size_t)be * Hv + h] = acc;
    }
}

// ---------------------------------------------------------------------------
// Generic NT GEMM: C[M,N] (+)= A[M,K](lda) * B[N,K](ldb)^T (+bias[n])
// dims must be multiples of 64/64/16 (true for all uses here)
// ---------------------------------------------------------------------------
__global__ __launch_bounds__(256)
void gemm_nt_kernel(int Kdim,
                    const float* __restrict__ A, int lda,
                    const float* __restrict__ Bm, int ldb,
                    float* __restrict__ C, int ldc,
                    const float* __restrict__ bias, int accumulate)
{
    const int BM = 64, BN = 64, BK = 16;
    __shared__ __align__(16) float As[BK][BM];
    __shared__ __align__(16) float Bs[BK][BN];

    const int tid = threadIdx.x;
    const int tx  = tid & 15;
    const int ty  = tid >> 4;
    const int m0  = blockIdx.y * BM;
    const int n0  = blockIdx.x * BN;
    const int lrow = tid >> 2;
    const int lc4  = (tid & 3) * 4;

    const float* aptr = A  + (size_t)(m0 + lrow) * lda;
    const float* bptr = Bm + (size_t)(n0 + lrow) * ldb;

    float acc[4][4] = {};
    for (int k0 = 0; k0 < Kdim; k0 += BK) {
        float4 a4 = *(const float4*)(aptr + k0 + lc4);
        float4 b4 = *(const float4*)(bptr + k0 + lc4);
        As[lc4+0][lrow] = a4.x; As[lc4+1][lrow] = a4.y;
        As[lc4+2][lrow] = a4.z; As[lc4+3][lrow] = a4.w;
        Bs[lc4+0][lrow] = b4.x; Bs[lc4+1][lrow] = b4.y;
        Bs[lc4+2][lrow] = b4.z; Bs[lc4+3][lrow] = b4.w;
        __syncthreads();
        #pragma unroll
        for (int k = 0; k < BK; k++) {
            float4 a = *(const float4*)&As[k][ty*4];
            float4 bb = *(const float4*)&Bs[k][tx*4];
            float ar[4] = {a.x, a.y, a.z, a.w};
            float br_[4] = {bb.x, bb.y, bb.z, bb.w};
            #pragma unroll
            for (int i = 0; i < 4; i++)
                #pragma unroll
                for (int j = 0; j < 4; j++)
                    acc[i][j] += ar[i] * br_[j];
        }
        __syncthreads();
    }
    #pragma unroll
    for (int i = 0; i < 4; i++) {
        int mrow = m0 + ty*4 + i;
        #pragma unroll
        for (int j = 0; j < 4; j++) {
            int n = n0 + tx*4 + j;
            float v = acc[i][j];
            if (accumulate) v += C[(size_t)mrow * ldc + n];
            if (bias)       v += bias[n];
            C[(size_t)mrow * ldc + n] = v;
        }
    }
}

// ---------------------------------------------------------------------------
// Generic NN GEMM: C[M,N] = A[M,K](lda) * B[K,N](ldb)
// ---------------------------------------------------------------------------
__global__ __launch_bounds__(256)
void gemm_nn_kernel(int Kdim,
                    const float* __restrict__ A, int lda,
                    const float* __restrict__ Bm, int ldb,
                    float* __restrict__ C, int ldc)
{
    const int BM = 64, BN = 64, BK = 16;
    __shared__ __align__(16) float As[BK][BM];
    __shared__ __align__(16) float Bs[BK][BN];

    const int tid = threadIdx.x;
    const int tx  = tid & 15;
    const int ty  = tid >> 4;
    const int m0  = blockIdx.y * BM;
    const int n0  = blockIdx.x * BN;
    const int lrow = tid >> 2;
    const int lc4  = (tid & 3) * 4;
    const int bk   = tid >> 4;          // 0..15 : k-row of B tile
    const int bn4  = (tid & 15) * 4;    // 0..60 : n within tile

    const float* aptr = A + (size_t)(m0 + lrow) * lda;

    float acc[4][4] = {};
    for (int k0 = 0; k0 < Kdim; k0 += BK) {
        float4 a4 = *(const float4*)(aptr + k0 + lc4);
        float4 b4 = *(const float4*)(Bm + (size_t)(k0 + bk) * ldb + n0 + bn4);
        As[lc4+0][lrow] = a4.x; As[lc4+1][lrow] = a4.y;
        As[lc4+2][lrow] = a4.z; As[lc4+3][lrow] = a4.w;
        Bs[bk][bn4+0] = b4.x; Bs[bk][bn4+1] = b4.y;
        Bs[bk][bn4+2] = b4.z; Bs[bk][bn4+3] = b4.w;
        __syncthreads();
        #pragma unroll
        for (int k = 0; k < BK; k++) {
            float4 a = *(const float4*)&As[k][ty*4];
            float4 bb = *(const float4*)&Bs[k][tx*4];
            float ar[4] = {a.x, a.y, a.z, a.w};
            float br_[4] = {bb.x, bb.y, bb.z, bb.w};
            #pragma unroll
            for (int i = 0; i < 4; i++)
                #pragma unroll
                for (int j = 0; j < 4; j++)
                    acc[i][j] += ar[i] * br_[j];
        }
        __syncthreads();
    }
    #pragma unroll
    for (int i = 0; i < 4; i++) {
        int mrow = m0 + ty*4 + i;
        #pragma unroll
        for (int j = 0; j < 4; j++)
            C[(size_t)mrow * ldc + (n0 + tx*4 + j)] = acc[i][j];
    }
}

// ---------------------------------------------------------------------------
extern "C" void kernel_launch(void* const* d_in, const int* in_sizes, int n_in,
                              void* d_out, int out_size)
{
    const float* mention  = (const float*)d_in[0];
    const int*   entities = (const int*)  d_in[1];
    const int*   masks    = (const int*)  d_in[2];
    const float* RM       = (const float*)d_in[3];
    const float* Wv       = (const float*)d_in[4];
    const float* bv       = (const float*)d_in[5];
    const float* Wu       = (const float*)d_in[6];
    const float* bu       = (const float*)d_in[7];
    const float* Wa       = (const float*)d_in[8];
    // d_in[9] = ba : additive constant inside softmax -> no-op, skipped
    const float* Wr       = (const float*)d_in[10];
    const float* br       = (const float*)d_in[11];
    const float* Wo       = (const float*)d_in[12];
    const float* bo       = (const float*)d_in[13];
    float* out = (float*)d_out;

    float *p_er, *p_sw, *p_s, *p_s2;
    cudaGetSymbolAddress((void**)&p_er, g_er);
    cudaGetSymbolAddress((void**)&p_sw, g_sw);
    cudaGetSymbolAddress((void**)&p_s,  g_s);
    cudaGetSymbolAddress((void**)&p_s2, g_s2);

    // 1. zero logits
    zero_logits_kernel<<<(MROWS + 255) / 256, 256>>>();

    // 2. fused gather + gated MIL attention GEMMs -> logits
    {
        dim3 grid(Av / 64, MROWS / 64);   // (4, 256)
        gated_mil_kernel<<<grid, 256>>>(mention, entities, Wv, bv, Wu, bu, Wa);
    }

    // 3. masked softmax over K + weighted pooling -> entity_reprs [1024,1024]
    softmax_pool_kernel<<<NBE, 256>>>(mention, entities, masks);

    // 4. s_w[R,H] = RM[R,RMS] @ Wr[H,RMS]^T + br   (NT)
    {
        dim3 grid(Hv / 64, Rv / 64);
        gemm_nt_kernel<<<grid, 256>>>(RMSv, RM, RMSv, Wr, RMSv, p_sw, Hv, br, 0);
    }

    // 5. s[BE,R] = ER[BE,H] @ s_w[R,H]^T   (NT)
    {
        dim3 grid(Rv / 64, NBE / 64);
        gemm_nt_kernel<<<grid, 256>>>(Hv, p_er, Hv, p_sw, Hv, p_s, Rv, nullptr, 0);
    }

    // 6. s2[BE,RMS] = s[BE,R] @ RM[R,RMS]   (NN)
    {
        dim3 grid(RMSv / 64, NBE / 64);
        gemm_nn_kernel<<<grid, 256>>>(Rv, p_s, Rv, RM, RMSv, p_s2, RMSv);
    }

    // 7. out = ER @ Wo[:, :H]^T            (NT, write)
    {
        dim3 grid(Hv / 64, NBE / 64);
        gemm_nt_kernel<<<grid, 256>>>(Hv, p_er, Hv, Wo, Hv + RMSv, out, Hv, nullptr, 0);
    }
    // 8. out += s2 @ Wo[:, H:]^T + bo      (NT, accumulate + bias)
    {
        dim3 grid(Hv / 64, NBE / 64);
        gemm_nt_kernel<<<grid, 256>>>(RMSv, p_s2, RMSv, Wo + Hv, Hv + RMSv, out, Hv, bo, 1);
    }
}

// round 3
// speedup vs baseline: 1.7226x; 1.7226x over previous
#include <cuda_runtime.h>
#include <cuda_bf16.h>
#include <math.h>
#include <stdint.h>

// ---------------- problem constants ----------------
#define Bv   8
#define Mv   256
#define Ev   128
#define Kv   16
#define Hv   1024
#define Av   256
#define Rv   1024
#define RMSv 512
#define NEGV (-1e25f)
#define MROWS (Bv*Ev*Kv)   // 16384
#define NBE   (Bv*Ev)      // 1024

// ---------------- scratch (static device globals) ----------------
__device__ float g_aV[MROWS * Av];
__device__ float g_aU[MROWS * Av];
__device__ float g_logits[MROWS];
__device__ float g_er[NBE * Hv];
__device__ float g_sw[Rv * Hv];
__device__ float g_s [NBE * Rv];
__device__ float g_s2[NBE * RMSv];
__device__ float g_rmT[RMSv * Rv];     // relation_memory^T

// ---------------- helpers ----------------
__device__ __forceinline__ uint32_t smem_u32(const void* p) {
    uint32_t a;
    asm("{ .reg .u64 t; cvta.to.shared.u64 t, %1; cvt.u32.u64 %0, t; }" : "=r"(a) : "l"(p));
    return a;
}
__device__ __forceinline__ uint32_t pack_bf16x2(float x, float y) {
    __nv_bfloat162 h = __floats2bfloat162_rn(x, y);
    return *(uint32_t*)&h;
}
__device__ __forceinline__ float bf16_round(float x) {
    return __bfloat162float(__float2bfloat16(x));
}

#define LDMATRIX_X4(r0, r1, r2, r3, addr) \
    asm volatile("ldmatrix.sync.aligned.m8n8.x4.shared.b16 {%0,%1,%2,%3}, [%4];" \
        : "=r"(r0), "=r"(r1), "=r"(r2), "=r"(r3) : "r"(addr))

#define MMA_BF16(c, a, b) \
    asm volatile("mma.sync.aligned.m16n8k16.row.col.f32.bf16.bf16.f32 " \
        "{%0,%1,%2,%3}, {%4,%5,%6,%7}, {%8,%9}, {%0,%1,%2,%3};" \
        : "+f"((c)[0]), "+f"((c)[1]), "+f"((c)[2]), "+f"((c)[3]) \
        : "r"((a)[0]), "r"((a)[1]), "r"((a)[2]), "r"((a)[3]), "r"((b)[0]), "r"((b)[1]))

// ---------------------------------------------------------------------------
// NT GEMM with bf16x3 fp32 emulation on mma.sync tensor cores.
// C[M,N] (+)= A[M,K](lda) * B[N,K](ldb)^T (+bias[n])
// BM in {64,128}, BN=128, BK=32. 256 threads (8 warps).
// If gatherIdx != null: A row gm -> mention row (gm>>11)*Mv + gatherIdx[gm].
// ---------------------------------------------------------------------------
template<int BM>
__global__ __launch_bounds__(256)
void gemm_bf16x3_nt(int Kdim,
                    const float* __restrict__ A, int lda,
                    const int* __restrict__ gatherIdx,
                    const float* __restrict__ B, int ldb,
                    float* __restrict__ C, int ldc,
                    const float* __restrict__ bias, int accumulate)
{
    constexpr int BN = 128;
    constexpr int WARPS_M = BM / 32;          // 4 or 2
    constexpr int WARPS_N = 8 / WARPS_M;      // 2 or 4
    constexpr int WN = BN / WARPS_N;          // 64 or 32
    constexpr int NT = WN / 8;                // 8 or 4
    constexpr int LD = 40;                    // bf16 per row (80B, conflict-free pad)

    __shared__ __align__(16) __nv_bfloat16 sA[2][BM][LD];   // [hi/lo]
    __shared__ __align__(16) __nv_bfloat16 sB[2][BN][LD];

    const int tid  = threadIdx.x;
    const int wid  = tid >> 5;
    const int lane = tid & 31;
    const int warp_m = wid % WARPS_M;
    const int warp_n = wid / WARPS_M;
    const int m0 = blockIdx.y * BM;
    const int n0 = blockIdx.x * BN;

    float cfr[2][NT][4];
    #pragma unroll
    for (int mt = 0; mt < 2; mt++)
        #pragma unroll
        for (int nt = 0; nt < NT; nt++)
            #pragma unroll
            for (int q = 0; q < 4; q++) cfr[mt][nt][q] = 0.0f;

    for (int k0 = 0; k0 < Kdim; k0 += 32) {
        // ---- fill A tile (BM x 32 fp32 -> bf16 hi/lo) ----
        #pragma unroll
        for (int it = 0; it < (BM * 8) / 256; it++) {
            int lin = it * 256 + tid;
            int row = lin >> 3;
            int c4  = (lin & 7) << 2;
            int gm  = m0 + row;
            const float* src;
            if (gatherIdx) {
                int b = gm >> 11;                        // / (E*K)=2048
                src = A + (size_t)(b * Mv + gatherIdx[gm]) * lda + k0 + c4;
            } else {
                src = A + (size_t)gm * lda + k0 + c4;
            }
            float4 v = *(const float4*)src;
            float hx = bf16_round(v.x), hy = bf16_round(v.y);
            float hz = bf16_round(v.z), hw = bf16_round(v.w);
            uint2 hi, lo;
            hi.x = pack_bf16x2(hx, hy);         hi.y = pack_bf16x2(hz, hw);
            lo.x = pack_bf16x2(v.x-hx, v.y-hy); lo.y = pack_bf16x2(v.z-hz, v.w-hw);
            *(uint2*)&sA[0][row][c4] = hi;
            *(uint2*)&sA[1][row][c4] = lo;
        }
        // ---- fill B tile (BN x 32) ----
        #pragma unroll
        for (int it = 0; it < (BN * 8) / 256; it++) {
            int lin = it * 256 + tid;
            int row = lin >> 3;
            int c4  = (lin & 7) << 2;
            const float* src = B + (size_t)(n0 + row) * ldb + k0 + c4;
            float4 v = *(const float4*)src;
            float hx = bf16_round(v.x), hy = bf16_round(v.y);
            float hz = bf16_round(v.z), hw = bf16_round(v.w);
            uint2 hi, lo;
            hi.x = pack_bf16x2(hx, hy);         hi.y = pack_bf16x2(hz, hw);
            lo.x = pack_bf16x2(v.x-hx, v.y-hy); lo.y = pack_bf16x2(v.z-hz, v.w-hw);
            *(uint2*)&sB[0][row][c4] = hi;
            *(uint2*)&sB[1][row][c4] = lo;
        }
        __syncthreads();

        // ---- compute: 2 k-steps x 3 split combos ----
        #pragma unroll
        for (int ks = 0; ks < 2; ks++) {
            #pragma unroll
            for (int s = 0; s < 3; s++) {
                const int as = (s == 2) ? 1 : 0;   // A split select
                const int bs = (s == 1) ? 1 : 0;   // B split select
                uint32_t af[2][4];
                #pragma unroll
                for (int mt = 0; mt < 2; mt++) {
                    int row = warp_m * 32 + mt * 16 + (lane & 15);
                    int col = ks * 16 + ((lane >> 4) << 3);
                    uint32_t addr = smem_u32(&sA[as][row][col]);
                    LDMATRIX_X4(af[mt][0], af[mt][1], af[mt][2], af[mt][3], addr);
                }
                uint32_t bfr[NT][2];
                #pragma unroll
                for (int np = 0; np < NT / 2; np++) {
                    int row = warp_n * WN + np * 16 + (lane & 7) + ((lane >> 4) << 3);
                    int col = ks * 16 + (((lane >> 3) & 1) << 3);
                    uint32_t addr = smem_u32(&sB[bs][row][col]);
                    uint32_t r0, r1, r2, r3;
                    LDMATRIX_X4(r0, r1, r2, r3, addr);
                    bfr[np*2][0] = r0;   bfr[np*2][1] = r1;
                    bfr[np*2+1][0] = r2; bfr[np*2+1][1] = r3;
                }
                #pragma unroll
                for (int mt = 0; mt < 2; mt++)
                    #pragma unroll
                    for (int nt = 0; nt < NT; nt++)
                        MMA_BF16(cfr[mt][nt], af[mt], bfr[nt]);
            }
        }
        __syncthreads();
    }

    // ---- epilogue ----
    const int g = lane >> 2;
    const int t = lane & 3;
    #pragma unroll
    for (int mt = 0; mt < 2; mt++) {
        #pragma unroll
        for (int nt = 0; nt < NT; nt++) {
            int row = m0 + warp_m * 32 + mt * 16 + g;
            int col = n0 + warp_n * WN + nt * 8 + t * 2;
            float v0 = cfr[mt][nt][0], v1 = cfr[mt][nt][1];
            float v2 = cfr[mt][nt][2], v3 = cfr[mt][nt][3];
            float* p0 = &C[(size_t)row * ldc + col];
            float* p1 = &C[(size_t)(row + 8) * ldc + col];
            if (accumulate) {
                float2 o0 = *(float2*)p0, o1 = *(float2*)p1;
                v0 += o0.x; v1 += o0.y; v2 += o1.x; v3 += o1.y;
            }
            if (bias) {
                float b0 = bias[col], b1 = bias[col + 1];
                v0 += b0; v1 += b1; v2 += b0; v3 += b1;
            }
            *(float2*)p0 = make_float2(v0, v1);
            *(float2*)p1 = make_float2(v2, v3);
        }
    }
}

// ---------------- logits: tanh(aV+bv)*sigmoid(aU+bu) . Wa ----------------
__global__ __launch_bounds__(256)
void logits_kernel(const float* __restrict__ bv, const float* __restrict__ bu,
                   const float* __restrict__ Wa)
{
    int r = blockIdx.x * 8 + (threadIdx.x >> 5);
    int lane = threadIdx.x & 31;
    const float* pv = g_aV + (size_t)r * Av;
    const float* pu = g_aU + (size_t)r * Av;
    float s = 0.0f;
    #pragma unroll
    for (int j = 0; j < 8; j++) {
        int a = lane + j * 32;
        float tv = tanhf(pv[a] + bv[a]);
        float su = 1.0f / (1.0f + expf(-(pu[a] + bu[a])));
        s += tv * su * Wa[a];
    }
    #pragma unroll
    for (int o = 16; o > 0; o >>= 1) s += __shfl_xor_sync(0xFFFFFFFF, s, o);
    if (lane == 0) g_logits[r] = s;
}

// ---------------- masked softmax over K + weighted pooling ----------------
__global__ __launch_bounds__(256)
void softmax_pool_kernel(const float* __restrict__ mention,
                         const int*   __restrict__ entities,
                         const int*   __restrict__ masks)
{
    const int be = blockIdx.x;
    const int b  = be / Ev;
    __shared__ float w[Kv];
    __shared__ int   idx[Kv];
    const int tid = threadIdx.x;
    if (tid < Kv) {
        int r = be * Kv + tid;
        idx[tid] = entities[r];
        w[tid]   = masks[r] ? g_logits[r] : NEGV;
    }
    __syncthreads();
    if (tid == 0) {
        float mx = w[0];
        #pragma unroll
        for (int k = 1; k < Kv; k++) mx = fmaxf(mx, w[k]);
        float s = 0.0f;
        #pragma unroll
        for (int k = 0; k < Kv; k++) { float e = expf(w[k] - mx); w[k] = e; s += e; }
        float inv = 1.0f / s;
        #pragma unroll
        for (int k = 0; k < Kv; k++) w[k] *= inv;
    }
    __syncthreads();
    float ww[Kv]; int ii[Kv];
    #pragma unroll
    for (int k = 0; k < Kv; k++) { ww[k] = w[k]; ii[k] = idx[k]; }
    const float* base = mention + (size_t)b * Mv * Hv;
    for (int h = tid; h < Hv; h += 256) {
        float acc = 0.0f;
        #pragma unroll
        for (int k = 0; k < Kv; k++)
            acc += ww[k] * base[(size_t)ii[k] * Hv + h];
        g_er[(size_t)be * Hv + h] = acc;
    }
}

// ---------------- transpose relation_memory: g_rmT[n,k] = RM[k,n] ----------------
__global__ void transpose_rm_kernel(const float* __restrict__ RM)
{
    __shared__ float tile[32][33];
    int tx = threadIdx.x, ty = threadIdx.y;
    int n0 = blockIdx.x * 32, k0 = blockIdx.y * 32;
    #pragma unroll
    for (int j = 0; j < 32; j += 8)
        tile[ty + j][tx] = RM[(size_t)(k0 + ty + j) * RMSv + n0 + tx];
    __syncthreads();
    #pragma unroll
    for (int j = 0; j < 32; j += 8)
        g_rmT[(size_t)(n0 + ty + j) * Rv + k0 + tx] = tile[tx][ty + j];
}

// ---------------- launch ----------------
extern "C" void kernel_launch(void* const* d_in, const int* in_sizes, int n_in,
                              void* d_out, int out_size)
{
    const float* mention  = (const float*)d_in[0];
    const int*   entities = (const int*)  d_in[1];
    const int*   masks    = (const int*)  d_in[2];
    const float* RM       = (const float*)d_in[3];
    const float* Wv       = (const float*)d_in[4];
    const float* bv       = (const float*)d_in[5];
    const float* Wu       = (const float*)d_in[6];
    const float* bu       = (const float*)d_in[7];
    const float* Wa       = (const float*)d_in[8];
    // d_in[9] = ba : additive constant inside softmax -> no-op
    const float* Wr       = (const float*)d_in[10];
    const float* br       = (const float*)d_in[11];
    const float* Wo       = (const float*)d_in[12];
    const float* bo       = (const float*)d_in[13];
    float* out = (float*)d_out;

    float *p_aV, *p_aU, *p_er, *p_sw, *p_s, *p_s2, *p_rmT;
    cudaGetSymbolAddress((void**)&p_aV,  g_aV);
    cudaGetSymbolAddress((void**)&p_aU,  g_aU);
    cudaGetSymbolAddress((void**)&p_er,  g_er);
    cudaGetSymbolAddress((void**)&p_sw,  g_sw);
    cudaGetSymbolAddress((void**)&p_s,   g_s);
    cudaGetSymbolAddress((void**)&p_s2,  g_s2);
    cudaGetSymbolAddress((void**)&p_rmT, g_rmT);

    // 1. transpose RM -> rmT [512, 1024]
    { dim3 g(RMSv / 32, Rv / 32), b(32, 8); transpose_rm_kernel<<<g, b>>>(RM); }

    // 2. aV = gather(X) @ Wv^T, aU = gather(X) @ Wu^T   [16384, 256]
    { dim3 g(Av / 128, MROWS / 128);   // (2, 128)
      gemm_bf16x3_nt<128><<<g, 256>>>(Hv, mention, Hv, entities, Wv, Hv, p_aV, Av, nullptr, 0);
      gemm_bf16x3_nt<128><<<g, 256>>>(Hv, mention, Hv, entities, Wu, Hv, p_aU, Av, nullptr, 0); }

    // 3. logits
    logits_kernel<<<MROWS / 8, 256>>>(bv, bu, Wa);

    // 4. softmax over K + pool -> entity_reprs [1024, 1024]
    softmax_pool_kernel<<<NBE, 256>>>(mention, entities, masks);

    // 5. sw = RM @ Wr^T + br   [1024(R), 1024(H)], K=512
    { dim3 g(Hv / 128, Rv / 64);
      gemm_bf16x3_nt<64><<<g, 256>>>(RMSv, RM, RMSv, nullptr, Wr, RMSv, p_sw, Hv, br, 0); }

    // 6. s = ER @ sw^T   [1024, 1024], K=1024
    { dim3 g(Rv / 128, NBE / 64);
      gemm_bf16x3_nt<64><<<g, 256>>>(Hv, p_er, Hv, nullptr, p_sw, Hv, p_s, Rv, nullptr, 0); }

    // 7. s2 = s @ rmT^T   [1024, 512], K=1024
    { dim3 g(RMSv / 128, NBE / 64);
      gemm_bf16x3_nt<64><<<g, 256>>>(Rv, p_s, Rv, nullptr, p_rmT, Rv, p_s2, RMSv, nullptr, 0); }

    // 8. out = ER @ Wo[:, :H]^T   [1024, 1024], K=1024 (ldb = H+RMS)
    { dim3 g(Hv / 128, NBE / 64);
      gemm_bf16x3_nt<64><<<g, 256>>>(Hv, p_er, Hv, nullptr, Wo, Hv + RMSv, out, Hv, nullptr, 0); }

    // 9. out += s2 @ Wo[:, H:]^T + bo   K=512
    { dim3 g(Hv / 128, NBE / 64);
      gemm_bf16x3_nt<64><<<g, 256>>>(RMSv, p_s2, RMSv, nullptr, Wo + Hv, Hv + RMSv, out, Hv, bo, 1); }
}

// round 4
// speedup vs baseline: 4.9005x; 2.8449x over previous
#include <cuda_runtime.h>
#include <cuda_bf16.h>
#include <math.h>
#include <stdint.h>

// ---------------- problem constants ----------------
#define Bv   8
#define Mv   256
#define Ev   128
#define Kv   16
#define Hv   1024
#define Av   256
#define Rv   1024
#define RMSv 512
#define NEGV (-1e25f)
#define MROWS (Bv*Ev*Kv)   // 16384
#define NBE   (Bv*Ev)      // 1024
#define NMENT (Bv*Mv)      // 2048 distinct mention rows

// ---------------- scratch (static device globals) ----------------
__device__ float g_mv[NMENT * Av];     // per-mention V projection (2 MB)
__device__ float g_mu[NMENT * Av];     // per-mention U projection (2 MB)
__device__ float g_gate[NMENT];        // per-mention gate logit
__device__ float g_er[NBE * Hv];
__device__ float g_sw[Rv * Hv];
__device__ float g_s [NBE * Rv];
__device__ float g_s2[NBE * RMSv];
__device__ float g_rmT[RMSv * Rv];     // relation_memory^T

// ---------------- helpers ----------------
__device__ __forceinline__ uint32_t smem_u32(const void* p) {
    uint32_t a;
    asm("{ .reg .u64 t; cvta.to.shared.u64 t, %1; cvt.u32.u64 %0, t; }" : "=r"(a) : "l"(p));
    return a;
}
__device__ __forceinline__ uint32_t pack_bf16x2(float x, float y) {
    __nv_bfloat162 h = __floats2bfloat162_rn(x, y);
    return *(uint32_t*)&h;
}
__device__ __forceinline__ float bf16_round(float x) {
    return __bfloat162float(__float2bfloat16(x));
}

#define LDMATRIX_X4(r0, r1, r2, r3, addr) \
    asm volatile("ldmatrix.sync.aligned.m8n8.x4.shared.b16 {%0,%1,%2,%3}, [%4];" \
        : "=r"(r0), "=r"(r1), "=r"(r2), "=r"(r3) : "r"(addr))

#define MMA_BF16(c, a, b) \
    asm volatile("mma.sync.aligned.m16n8k16.row.col.f32.bf16.bf16.f32 " \
        "{%0,%1,%2,%3}, {%4,%5,%6,%7}, {%8,%9}, {%0,%1,%2,%3};" \
        : "+f"((c)[0]), "+f"((c)[1]), "+f"((c)[2]), "+f"((c)[3]) \
        : "r"((a)[0]), "r"((a)[1]), "r"((a)[2]), "r"((a)[3]), "r"((b)[0]), "r"((b)[1]))

// ---------------------------------------------------------------------------
// NT GEMM, bf16x3 fp32 emulation, register-staged prefetch, fragment reuse.
// C[M,N] (+)= A[M,K](lda) * B[N,K](ldb)^T (+bias[n])
// BM=64, BN=128, BK=32, 256 threads (8 warps, 2x4 warp grid).
// N-split: blocks with blockIdx.x >= nsplit use B2/C2 (for fused Wv|Wu call).
// ---------------------------------------------------------------------------
__global__ __launch_bounds__(256)
void gemm_bf16x3_nt(int Kdim,
                    const float* __restrict__ A, int lda,
                    const float* __restrict__ B1, const float* __restrict__ B2,
                    int nsplit, int ldb,
                    float* __restrict__ C1, float* __restrict__ C2, int ldc,
                    const float* __restrict__ bias, int accumulate)
{
    constexpr int BM = 64, BN = 128;
    constexpr int WARPS_M = 2, WARPS_N = 4;
    constexpr int WN = BN / WARPS_N;      // 32
    constexpr int NT = WN / 8;            // 4
    constexpr int LD = 40;                // 80B rows, conflict-free
    constexpr int AIT = (BM * 8) / 256;   // 2 float4 per thread
    constexpr int BIT = (BN * 8) / 256;   // 4 float4 per thread

    __shared__ __align__(16) __nv_bfloat16 sA[2][BM][LD];
    __shared__ __align__(16) __nv_bfloat16 sB[2][BN][LD];

    const int tid  = threadIdx.x;
    const int wid  = tid >> 5;
    const int lane = tid & 31;
    const int warp_m = wid % WARPS_M;
    const int warp_n = wid / WARPS_M;
    const int m0 = blockIdx.y * BM;

    const bool second = ((int)blockIdx.x >= nsplit);
    const float* Bp = second ? B2 : B1;
    float*       Cp = second ? C2 : C1;
    const int n0 = (second ? (blockIdx.x - nsplit) : blockIdx.x) * BN;

    // staging-load row/col (shared by A and B fills)
    const int srow = tid >> 3;            // 0..31
    const int sc4  = (tid & 7) << 2;      // 0..28

    float4 ra[AIT], rb[BIT];
    const float* aBase = A  + (size_t)(m0 + srow) * lda + sc4;
    const float* bBase = Bp + (size_t)(n0 + srow) * ldb + sc4;

    // preload chunk 0
    #pragma unroll
    for (int i = 0; i < AIT; i++) ra[i] = *(const float4*)(aBase + (size_t)(i * 32) * lda);
    #pragma unroll
    for (int i = 0; i < BIT; i++) rb[i] = *(const float4*)(bBase + (size_t)(i * 32) * ldb);

    float cfr[2][NT][4];
    #pragma unroll
    for (int mt = 0; mt < 2; mt++)
        #pragma unroll
        for (int nt = 0; nt < NT; nt++)
            #pragma unroll
            for (int q = 0; q < 4; q++) cfr[mt][nt][q] = 0.0f;

    const int nCh = Kdim >> 5;
    for (int ch = 0; ch < nCh; ch++) {
        // ---- convert staged regs -> smem (hi/lo bf16) ----
        #pragma unroll
        for (int i = 0; i < AIT; i++) {
            float4 v = ra[i];
            int row = i * 32 + srow;
            float hx = bf16_round(v.x), hy = bf16_round(v.y);
            float hz = bf16_round(v.z), hw = bf16_round(v.w);
            uint2 hi, lo;
            hi.x = pack_bf16x2(hx, hy);         hi.y = pack_bf16x2(hz, hw);
            lo.x = pack_bf16x2(v.x-hx, v.y-hy); lo.y = pack_bf16x2(v.z-hz, v.w-hw);
            *(uint2*)&sA[0][row][sc4] = hi;
            *(uint2*)&sA[1][row][sc4] = lo;
        }
        #pragma unroll
        for (int i = 0; i < BIT; i++) {
            float4 v = rb[i];
            int row = i * 32 + srow;
            float hx = bf16_round(v.x), hy = bf16_round(v.y);
            float hz = bf16_round(v.z), hw = bf16_round(v.w);
            uint2 hi, lo;
            hi.x = pack_bf16x2(hx, hy);         hi.y = pack_bf16x2(hz, hw);
            lo.x = pack_bf16x2(v.x-hx, v.y-hy); lo.y = pack_bf16x2(v.z-hz, v.w-hw);
            *(uint2*)&sB[0][row][sc4] = hi;
            *(uint2*)&sB[1][row][sc4] = lo;
        }
        __syncthreads();

        // ---- prefetch next chunk (LDGs overlap MMA below) ----
        if (ch + 1 < nCh) {
            int koff = (ch + 1) << 5;
            #pragma unroll
            for (int i = 0; i < AIT; i++) ra[i] = *(const float4*)(aBase + (size_t)(i * 32) * lda + koff);
            #pragma unroll
            for (int i = 0; i < BIT; i++) rb[i] = *(const float4*)(bBase + (size_t)(i * 32) * ldb + koff);
        }

        // ---- MMA: per k-step load afH,bfH,bfL,afL; 3 split products ----
        #pragma unroll
        for (int ks = 0; ks < 2; ks++) {
            uint32_t afH[2][4];
            #pragma unroll
            for (int mt = 0; mt < 2; mt++) {
                int row = warp_m * 32 + mt * 16 + (lane & 15);
                int col = ks * 16 + ((lane >> 4) << 3);
                LDMATRIX_X4(afH[mt][0], afH[mt][1], afH[mt][2], afH[mt][3],
                            smem_u32(&sA[0][row][col]));
            }
            uint32_t bfH[NT][2];
            #pragma unroll
            for (int np = 0; np < NT / 2; np++) {
                int row = warp_n * WN + np * 16 + (lane & 7) + ((lane >> 4) << 3);
                int col = ks * 16 + (((lane >> 3) & 1) << 3);
                uint32_t r0, r1, r2, r3;
                LDMATRIX_X4(r0, r1, r2, r3, smem_u32(&sB[0][row][col]));
                bfH[np*2][0] = r0;   bfH[np*2][1] = r1;
                bfH[np*2+1][0] = r2; bfH[np*2+1][1] = r3;
            }
            // s0: hi x hi
            #pragma unroll
            for (int mt = 0; mt < 2; mt++)
                #pragma unroll
                for (int nt = 0; nt < NT; nt++) MMA_BF16(cfr[mt][nt], afH[mt], bfH[nt]);
            // s1: hi x lo
            {
                uint32_t bfL[NT][2];
                #pragma unroll
                for (int np = 0; np < NT / 2; np++) {
                    int row = warp_n * WN + np * 16 + (lane & 7) + ((lane >> 4) << 3);
                    int col = ks * 16 + (((lane >> 3) & 1) << 3);
                    uint32_t r0, r1, r2, r3;
                    LDMATRIX_X4(r0, r1, r2, r3, smem_u32(&sB[1][row][col]));
                    bfL[np*2][0] = r0;   bfL[np*2][1] = r1;
                    bfL[np*2+1][0] = r2; bfL[np*2+1][1] = r3;
                }
                #pragma unroll
                for (int mt = 0; mt < 2; mt++)
                    #pragma unroll
                    for (int nt = 0; nt < NT; nt++) MMA_BF16(cfr[mt][nt], afH[mt], bfL[nt]);
            }
            // s2: lo x hi
            {
                uint32_t afL[2][4];
                #pragma unroll
                for (int mt = 0; mt < 2; mt++) {
                    int row = warp_m * 32 + mt * 16 + (lane & 15);
                    int col = ks * 16 + ((lane >> 4) << 3);
                    LDMATRIX_X4(afL[mt][0], afL[mt][1], afL[mt][2], afL[mt][3],
                                smem_u32(&sA[1][row][col]));
                }
                #pragma unroll
                for (int mt = 0; mt < 2; mt++)
                    #pragma unroll
                    for (int nt = 0; nt < NT; nt++) MMA_BF16(cfr[mt][nt], afL[mt], bfH[nt]);
            }
        }
        __syncthreads();
    }

    // ---- epilogue ----
    const int g = lane >> 2;
    const int t = lane & 3;
    #pragma unroll
    for (int mt = 0; mt < 2; mt++) {
        #pragma unroll
        for (int nt = 0; nt < NT; nt++) {
            int row = m0 + warp_m * 32 + mt * 16 + g;
            int col = n0 + warp_n * WN + nt * 8 + t * 2;
            float v0 = cfr[mt][nt][0], v1 = cfr[mt][nt][1];
            float v2 = cfr[mt][nt][2], v3 = cfr[mt][nt][3];
            float* p0 = &Cp[(size_t)row * ldc + col];
            float* p1 = &Cp[(size_t)(row + 8) * ldc + col];
            if (accumulate) {
                float2 o0 = *(float2*)p0, o1 = *(float2*)p1;
                v0 += o0.x; v1 += o0.y; v2 += o1.x; v3 += o1.y;
            }
            if (bias) {
                float b0 = bias[col], b1 = bias[col + 1];
                v0 += b0; v1 += b1; v2 += b0; v3 += b1;
            }
            *(float2*)p0 = make_float2(v0, v1);
            *(float2*)p1 = make_float2(v2, v3);
        }
    }
}

// ---------------- per-mention gate: tanh(mv+bv)*sigmoid(mu+bu) . Wa ----------------
__global__ __launch_bounds__(256)
void gate_kernel(const float* __restrict__ bv, const float* __restrict__ bu,
                 const float* __restrict__ Wa)
{
    int r = blockIdx.x * 8 + (threadIdx.x >> 5);     // mention row 0..2047
    int lane = threadIdx.x & 31;
    const float* pv = g_mv + (size_t)r * Av;
    const float* pu = g_mu + (size_t)r * Av;
    float s = 0.0f;
    #pragma unroll
    for (int j = 0; j < 8; j++) {
        int a = lane + j * 32;
        float tv = tanhf(pv[a] + bv[a]);
        float su = 1.0f / (1.0f + expf(-(pu[a] + bu[a])));
        s += tv * su * Wa[a];
    }
    #pragma unroll
    for (int o = 16; o > 0; o >>= 1) s += __shfl_xor_sync(0xFFFFFFFF, s, o);
    if (lane == 0) g_gate[r] = s;
}

// ---------------- masked softmax over K + weighted pooling ----------------
__global__ __launch_bounds__(256)
void softmax_pool_kernel(const float* __restrict__ mention,
                         const int*   __restrict__ entities,
                         const int*   __restrict__ masks)
{
    const int be = blockIdx.x;
    const int b  = be / Ev;
    __shared__ float w[Kv];
    __shared__ int   idx[Kv];
    const int tid = threadIdx.x;
    if (tid < Kv) {
        int r = be * Kv + tid;
        int m = entities[r];
        idx[tid] = m;
        w[tid]   = masks[r] ? g_gate[b * Mv + m] : NEGV;
    }
    __syncthreads();
    if (tid == 0) {
        float mx = w[0];
        #pragma unroll
        for (int k = 1; k < Kv; k++) mx = fmaxf(mx, w[k]);
        float s = 0.0f;
        #pragma unroll
        for (int k = 0; k < Kv; k++) { float e = expf(w[k] - mx); w[k] = e; s += e; }
        float inv = 1.0f / s;
        #pragma unroll
        for (int k = 0; k < Kv; k++) w[k] *= inv;
    }
    __syncthreads();
    float ww[Kv]; int ii[Kv];
    #pragma unroll
    for (int k = 0; k < Kv; k++) { ww[k] = w[k]; ii[k] = idx[k]; }
    const float* base = mention + (size_t)b * Mv * Hv;
    for (int h = tid; h < Hv; h += 256) {
        float acc = 0.0f;
        #pragma unroll
        for (int k = 0; k < Kv; k++)
            acc += ww[k] * base[(size_t)ii[k] * Hv + h];
        g_er[(size_t)be * Hv + h] = acc;
    }
}

// ---------------- transpose relation_memory: g_rmT[n,k] = RM[k,n] ----------------
__global__ void transpose_rm_kernel(const float* __restrict__ RM)
{
    __shared__ float tile[32][33];
    int tx = threadIdx.x, ty = threadIdx.y;
    int n0 = blockIdx.x * 32, k0 = blockIdx.y * 32;
    #pragma unroll
    for (int j = 0; j < 32; j += 8)
        tile[ty + j][tx] = RM[(size_t)(k0 + ty + j) * RMSv + n0 + tx];
    __syncthreads();
    #pragma unroll
    for (int j = 0; j < 32; j += 8)
        g_rmT[(size_t)(n0 + ty + j) * Rv + k0 + tx] = tile[tx][ty + j];
}

// ---------------- launch ----------------
extern "C" void kernel_launch(void* const* d_in, const int* in_sizes, int n_in,
                              void* d_out, int out_size)
{
    const float* mention  = (const float*)d_in[0];
    const int*   entities = (const int*)  d_in[1];
    const int*   masks    = (const int*)  d_in[2];
    const float* RM       = (const float*)d_in[3];
    const float* Wv       = (const float*)d_in[4];
    const float* bv       = (const float*)d_in[5];
    const float* Wu       = (const float*)d_in[6];
    const float* bu       = (const float*)d_in[7];
    const float* Wa       = (const float*)d_in[8];
    // d_in[9] = ba : additive constant inside softmax -> no-op
    const float* Wr       = (const float*)d_in[10];
    const float* br       = (const float*)d_in[11];
    const float* Wo       = (const float*)d_in[12];
    const float* bo       = (const float*)d_in[13];
    float* out = (float*)d_out;

    float *p_mv, *p_mu, *p_er, *p_sw, *p_s, *p_s2, *p_rmT;
    cudaGetSymbolAddress((void**)&p_mv,  g_mv);
    cudaGetSymbolAddress((void**)&p_mu,  g_mu);
    cudaGetSymbolAddress((void**)&p_er,  g_er);
    cudaGetSymbolAddress((void**)&p_sw,  g_sw);
    cudaGetSymbolAddress((void**)&p_s,   g_s);
    cudaGetSymbolAddress((void**)&p_s2,  g_s2);
    cudaGetSymbolAddress((void**)&p_rmT, g_rmT);

    const int BIG = 1 << 30;

    // 1. transpose RM -> rmT [512, 1024]
    { dim3 g(RMSv / 32, Rv / 32), b(32, 8); transpose_rm_kernel<<<g, b>>>(RM); }

    // 2. per-mention projections (fused): mv = mention@Wv^T, mu = mention@Wu^T
    //    [2048, 256], K=1024; grid x: blocks 0-1 -> Wv, 2-3 -> Wu
    { dim3 g(2 * (Av / 128), NMENT / 64);   // (4, 32)
      gemm_bf16x3_nt<<<g, 256>>>(Hv, mention, Hv, Wv, Wu, Av / 128, Hv,
                                 p_mv, p_mu, Av, nullptr, 0); }

    // 3. per-mention gate logit [2048]
    gate_kernel<<<NMENT / 8, 256>>>(bv, bu, Wa);

    // 4. softmax over K + pool -> entity_reprs [1024, 1024]
    softmax_pool_kernel<<<NBE, 256>>>(mention, entities, masks);

    // 5. sw = RM @ Wr^T + br   [1024(R), 1024(H)], K=512
    { dim3 g(Hv / 128, Rv / 64);
      gemm_bf16x3_nt<<<g, 256>>>(RMSv, RM, RMSv, Wr, Wr, BIG, RMSv,
                                 p_sw, p_sw, Hv, br, 0); }

    // 6. s = ER @ sw^T   [1024, 1024], K=1024
    { dim3 g(Rv / 128, NBE / 64);
      gemm_bf16x3_nt<<<g, 256>>>(Hv, p_er, Hv, p_sw, p_sw, BIG, Hv,
                                 p_s, p_s, Rv, nullptr, 0); }

    // 7. s2 = s @ rmT^T   [1024, 512], K=1024
    { dim3 g(RMSv / 128, NBE / 64);
      gemm_bf16x3_nt<<<g, 256>>>(Rv, p_s, Rv, p_rmT, p_rmT, BIG, Rv,
                                 p_s2, p_s2, RMSv, nullptr, 0); }

    // 8. out = ER @ Wo[:, :H]^T   [1024, 1024], K=1024 (ldb = H+RMS)
    { dim3 g(Hv / 128, NBE / 64);
      gemm_bf16x3_nt<<<g, 256>>>(Hv, p_er, Hv, Wo, Wo, BIG, Hv + RMSv,
                                 out, out, Hv, nullptr, 0); }

    // 9. out += s2 @ Wo[:, H:]^T + bo   K=512
    { dim3 g(Hv / 128, NBE / 64);
      gemm_bf16x3_nt<<<g, 256>>>(RMSv, p_s2, RMSv, Wo + Hv, Wo + Hv, BIG, Hv + RMSv,
                                 out, out, Hv, bo, 1); }
}

// round 5
// speedup vs baseline: 4.9343x; 1.0069x over previous
#include <cuda_runtime.h>
#include <cuda_bf16.h>
#include <math.h>
#include <stdint.h>

// ---------------- problem constants ----------------
#define Bv   8
#define Mv   256
#define Ev   128
#define Kv   16
#define Hv   1024
#define Av   256
#define Rv   1024
#define RMSv 512
#define NEGV (-1e25f)
#define MROWS (Bv*Ev*Kv)   // 16384
#define NBE   (Bv*Ev)      // 1024
#define NMENT (Bv*Mv)      // 2048 distinct mention rows

// ---------------- scratch (static device globals) ----------------
__device__ float g_mv[NMENT * Av];     // per-mention V projection (2 MB)
__device__ float g_mu[NMENT * Av];     // per-mention U projection (2 MB)
__device__ float g_gate[NMENT];        // per-mention gate logit
__device__ float g_er[NBE * Hv];
__device__ float g_sw[Rv * Hv];
__device__ float g_s [NBE * Rv];
__device__ float g_s2[NBE * RMSv];
__device__ float g_rmT[RMSv * Rv];     // relation_memory^T

// ---------------- helpers ----------------
__device__ __forceinline__ uint32_t smem_u32(const void* p) {
    uint32_t a;
    asm("{ .reg .u64 t; cvta.to.shared.u64 t, %1; cvt.u32.u64 %0, t; }" : "=r"(a) : "l"(p));
    return a;
}
__device__ __forceinline__ uint32_t pack_bf16x2(float x, float y) {
    __nv_bfloat162 h = __floats2bfloat162_rn(x, y);
    return *(uint32_t*)&h;
}
__device__ __forceinline__ float bf16_round(float x) {
    return __bfloat162float(__float2bfloat16(x));
}

#define LDMATRIX_X4(r0, r1, r2, r3, addr) \
    asm volatile("ldmatrix.sync.aligned.m8n8.x4.shared.b16 {%0,%1,%2,%3}, [%4];" \
        : "=r"(r0), "=r"(r1), "=r"(r2), "=r"(r3) : "r"(addr))

#define MMA_BF16(c, a, b) \
    asm volatile("mma.sync.aligned.m16n8k16.row.col.f32.bf16.bf16.f32 " \
        "{%0,%1,%2,%3}, {%4,%5,%6,%7}, {%8,%9}, {%0,%1,%2,%3};" \
        : "+f"((c)[0]), "+f"((c)[1]), "+f"((c)[2]), "+f"((c)[3]) \
        : "r"((a)[0]), "r"((a)[1]), "r"((a)[2]), "r"((a)[3]), "r"((b)[0]), "r"((b)[1]))

// ---------------------------------------------------------------------------
// NT GEMM, bf16x3 fp32 emulation, register-staged prefetch, fragment reuse.
// C[M,N] (+)= A[M,K](lda) * B[N,K](ldb)^T (+bias[n])
// BM=64, BN=128, BK=32, 256 threads (8 warps, 2x4 warp grid).
// N-split: blocks with blockIdx.x >= nsplit use B2/C2 (for fused Wv|Wu call).
// ---------------------------------------------------------------------------
__global__ __launch_bounds__(256)
void gemm_bf16x3_nt(int Kdim,
                    const float* __restrict__ A, int lda,
                    const float* __restrict__ B1, const float* __restrict__ B2,
                    int nsplit, int ldb,
                    float* __restrict__ C1, float* __restrict__ C2, int ldc,
                    const float* __restrict__ bias, int accumulate)
{
    constexpr int BM = 64, BN = 128;
    constexpr int WARPS_M = 2, WARPS_N = 4;
    constexpr int WN = BN / WARPS_N;      // 32
    constexpr int NT = WN / 8;            // 4
    constexpr int LD = 40;                // 80B rows, conflict-free
    constexpr int AIT = (BM * 8) / 256;   // 2 float4 per thread
    constexpr int BIT = (BN * 8) / 256;   // 4 float4 per thread

    __shared__ __align__(16) __nv_bfloat16 sA[2][BM][LD];
    __shared__ __align__(16) __nv_bfloat16 sB[2][BN][LD];

    const int tid  = threadIdx.x;
    const int wid  = tid >> 5;
    const int lane = tid & 31;
    const int warp_m = wid % WARPS_M;
    const int warp_n = wid / WARPS_M;
    const int m0 = blockIdx.y * BM;

    const bool second = ((int)blockIdx.x >= nsplit);
    const float* Bp = second ? B2 : B1;
    float*       Cp = second ? C2 : C1;
    const int n0 = (second ? (blockIdx.x - nsplit) : blockIdx.x) * BN;

    // staging-load row/col (shared by A and B fills)
    const int srow = tid >> 3;            // 0..31
    const int sc4  = (tid & 7) << 2;      // 0..28

    float4 ra[AIT], rb[BIT];
    const float* aBase = A  + (size_t)(m0 + srow) * lda + sc4;
    const float* bBase = Bp + (size_t)(n0 + srow) * ldb + sc4;

    // preload chunk 0
    #pragma unroll
    for (int i = 0; i < AIT; i++) ra[i] = *(const float4*)(aBase + (size_t)(i * 32) * lda);
    #pragma unroll
    for (int i = 0; i < BIT; i++) rb[i] = *(const float4*)(bBase + (size_t)(i * 32) * ldb);

    float cfr[2][NT][4];
    #pragma unroll
    for (int mt = 0; mt < 2; mt++)
        #pragma unroll
        for (int nt = 0; nt < NT; nt++)
            #pragma unroll
            for (int q = 0; q < 4; q++) cfr[mt][nt][q] = 0.0f;

    const int nCh = Kdim >> 5;
    for (int ch = 0; ch < nCh; ch++) {
        // ---- convert staged regs -> smem (hi/lo bf16) ----
        #pragma unroll
        for (int i = 0; i < AIT; i++) {
            float4 v = ra[i];
            int row = i * 32 + srow;
            float hx = bf16_round(v.x), hy = bf16_round(v.y);
            float hz = bf16_round(v.z), hw = bf16_round(v.w);
            uint2 hi, lo;
            hi.x = pack_bf16x2(hx, hy);         hi.y = pack_bf16x2(hz, hw);
            lo.x = pack_bf16x2(v.x-hx, v.y-hy); lo.y = pack_bf16x2(v.z-hz, v.w-hw);
            *(uint2*)&sA[0][row][sc4] = hi;
            *(uint2*)&sA[1][row][sc4] = lo;
        }
        #pragma unroll
        for (int i = 0; i < BIT; i++) {
            float4 v = rb[i];
            int row = i * 32 + srow;
            float hx = bf16_round(v.x), hy = bf16_round(v.y);
            float hz = bf16_round(v.z), hw = bf16_round(v.w);
            uint2 hi, lo;
            hi.x = pack_bf16x2(hx, hy);         hi.y = pack_bf16x2(hz, hw);
            lo.x = pack_bf16x2(v.x-hx, v.y-hy); lo.y = pack_bf16x2(v.z-hz, v.w-hw);
            *(uint2*)&sB[0][row][sc4] = hi;
            *(uint2*)&sB[1][row][sc4] = lo;
        }
        __syncthreads();

        // ---- prefetch next chunk (LDGs overlap MMA below) ----
        if (ch + 1 < nCh) {
            int koff = (ch + 1) << 5;
            #pragma unroll
            for (int i = 0; i < AIT; i++) ra[i] = *(const float4*)(aBase + (size_t)(i * 32) * lda + koff);
            #pragma unroll
            for (int i = 0; i < BIT; i++) rb[i] = *(const float4*)(bBase + (size_t)(i * 32) * ldb + koff);
        }

        // ---- MMA: per k-step load afH,bfH,bfL,afL; 3 split products ----
        #pragma unroll
        for (int ks = 0; ks < 2; ks++) {
            uint32_t afH[2][4];
            #pragma unroll
            for (int mt = 0; mt < 2; mt++) {
                int row = warp_m * 32 + mt * 16 + (lane & 15);
                int col = ks * 16 + ((lane >> 4) << 3);
                LDMATRIX_X4(afH[mt][0], afH[mt][1], afH[mt][2], afH[mt][3],
                            smem_u32(&sA[0][row][col]));
            }
            uint32_t bfH[NT][2];
            #pragma unroll
            for (int np = 0; np < NT / 2; np++) {
                int row = warp_n * WN + np * 16 + (lane & 7) + ((lane >> 4) << 3);
                int col = ks * 16 + (((lane >> 3) & 1) << 3);
                uint32_t r0, r1, r2, r3;
                LDMATRIX_X4(r0, r1, r2, r3, smem_u32(&sB[0][row][col]));
                bfH[np*2][0] = r0;   bfH[np*2][1] = r1;
                bfH[np*2+1][0] = r2; bfH[np*2+1][1] = r3;
            }
            // s0: hi x hi
            #pragma unroll
            for (int mt = 0; mt < 2; mt++)
                #pragma unroll
                for (int nt = 0; nt < NT; nt++) MMA_BF16(cfr[mt][nt], afH[mt], bfH[nt]);
            // s1: hi x lo
            {
                uint32_t bfL[NT][2];
                #pragma unroll
                for (int np = 0; np < NT / 2; np++) {
                    int row = warp_n * WN + np * 16 + (lane & 7) + ((lane >> 4) << 3);
                    int col = ks * 16 + (((lane >> 3) & 1) << 3);
                    uint32_t r0, r1, r2, r3;
                    LDMATRIX_X4(r0, r1, r2, r3, smem_u32(&sB[1][row][col]));
                    bfL[np*2][0] = r0;   bfL[np*2][1] = r1;
                    bfL[np*2+1][0] = r2; bfL[np*2+1][1] = r3;
                }
                #pragma unroll
                for (int mt = 0; mt < 2; mt++)
                    #pragma unroll
                    for (int nt = 0; nt < NT; nt++) MMA_BF16(cfr[mt][nt], afH[mt], bfL[nt]);
            }
            // s2: lo x hi
            {
                uint32_t afL[2][4];
                #pragma unroll
                for (int mt = 0; mt < 2; mt++) {
                    int row = warp_m * 32 + mt * 16 + (lane & 15);
                    int col = ks * 16 + ((lane >> 4) << 3);
                    LDMATRIX_X4(afL[mt][0], afL[mt][1], afL[mt][2], afL[mt][3],
                                smem_u32(&sA[1][row][col]));
                }
                #pragma unroll
                for (int mt = 0; mt < 2; mt++)
                    #pragma unroll
                    for (int nt = 0; nt < NT; nt++) MMA_BF16(cfr[mt][nt], afL[mt], bfH[nt]);
            }
        }
        __syncthreads();
    }

    // ---- epilogue ----
    const int g = lane >> 2;
    const int t = lane & 3;
    #pragma unroll
    for (int mt = 0; mt < 2; mt++) {
        #pragma unroll
        for (int nt = 0; nt < NT; nt++) {
            int row = m0 + warp_m * 32 + mt * 16 + g;
            int col = n0 + warp_n * WN + nt * 8 + t * 2;
            float v0 = cfr[mt][nt][0], v1 = cfr[mt][nt][1];
            float v2 = cfr[mt][nt][2], v3 = cfr[mt][nt][3];
            float* p0 = &Cp[(size_t)row * ldc + col];
            float* p1 = &Cp[(size_t)(row + 8) * ldc + col];
            if (accumulate) {
                float2 o0 = *(float2*)p0, o1 = *(float2*)p1;
                v0 += o0.x; v1 += o0.y; v2 += o1.x; v3 += o1.y;
            }
            if (bias) {
                float b0 = bias[col], b1 = bias[col + 1];
                v0 += b0; v1 += b1; v2 += b0; v3 += b1;
            }
            *(float2*)p0 = make_float2(v0, v1);
            *(float2*)p1 = make_float2(v2, v3);
        }
    }
}

// ---------------- per-mention gate: tanh(mv+bv)*sigmoid(mu+bu) . Wa ----------------
__global__ __launch_bounds__(256)
void gate_kernel(const float* __restrict__ bv, const float* __restrict__ bu,
                 const float* __restrict__ Wa)
{
    int r = blockIdx.x * 8 + (threadIdx.x >> 5);     // mention row 0..2047
    int lane = threadIdx.x & 31;
    const float* pv = g_mv + (size_t)r * Av;
    const float* pu = g_mu + (size_t)r * Av;
    float s = 0.0f;
    #pragma unroll
    for (int j = 0; j < 8; j++) {
        int a = lane + j * 32;
        float tv = tanhf(pv[a] + bv[a]);
        float su = 1.0f / (1.0f + expf(-(pu[a] + bu[a])));
        s += tv * su * Wa[a];
    }
    #pragma unroll
    for (int o = 16; o > 0; o >>= 1) s += __shfl_xor_sync(0xFFFFFFFF, s, o);
    if (lane == 0) g_gate[r] = s;
}

// ---------------- masked softmax over K + weighted pooling ----------------
__global__ __launch_bounds__(256)
void softmax_pool_kernel(const float* __restrict__ mention,
                         const int*   __restrict__ entities,
                         const int*   __restrict__ masks)
{
    const int be = blockIdx.x;
    const int b  = be / Ev;
    __shared__ float w[Kv];
    __shared__ int   idx[Kv];
    const int tid = threadIdx.x;
    if (tid < Kv) {
        int r = be * Kv + tid;
        int m = entities[r];
        idx[tid] = m;
        w[tid]   = masks[r] ? g_gate[b * Mv + m] : NEGV;
    }
    __syncthreads();
    if (tid == 0) {
        float mx = w[0];
        #pragma unroll
        for (int k = 1; k < Kv; k++) mx = fmaxf(mx, w[k]);
        float s = 0.0f;
        #pragma unroll
        for (int k = 0; k < Kv; k++) { float e = expf(w[k] - mx); w[k] = e; s += e; }
        float inv = 1.0f / s;
        #pragma unroll
        for (int k = 0; k < Kv; k++) w[k] *= inv;
    }
    __syncthreads();
    float ww[Kv]; int ii[Kv];
    #pragma unroll
    for (int k = 0; k < Kv; k++) { ww[k] = w[k]; ii[k] = idx[k]; }
    const float* base = mention + (size_t)b * Mv * Hv;
    for (int h = tid; h < Hv; h += 256) {
        float acc = 0.0f;
        #pragma unroll
        for (int k = 0; k < Kv; k++)
            acc += ww[k] * base[(size_t)ii[k] * Hv + h];
        g_er[(size_t)be * Hv + h] = acc;
    }
}

// ---------------- transpose relation_memory: g_rmT[n,k] = RM[k,n] ----------------
__global__ void transpose_rm_kernel(const float* __restrict__ RM)
{
    __shared__ float tile[32][33];
    int tx = threadIdx.x, ty = threadIdx.y;
    int n0 = blockIdx.x * 32, k0 = blockIdx.y * 32;
    #pragma unroll
    for (int j = 0; j < 32; j += 8)
        tile[ty + j][tx] = RM[(size_t)(k0 + ty + j) * RMSv + n0 + tx];
    __syncthreads();
    #pragma unroll
    for (int j = 0; j < 32; j += 8)
        g_rmT[(size_t)(n0 + ty + j) * Rv + k0 + tx] = tile[tx][ty + j];
}

// ---------------- launch ----------------
extern "C" void kernel_launch(void* const* d_in, const int* in_sizes, int n_in,
                              void* d_out, int out_size)
{
    const float* mention  = (const float*)d_in[0];
    const int*   entities = (const int*)  d_in[1];
    const int*   masks    = (const int*)  d_in[2];
    const float* RM       = (const float*)d_in[3];
    const float* Wv       = (const float*)d_in[4];
    const float* bv       = (const float*)d_in[5];
    const float* Wu       = (const float*)d_in[6];
    const float* bu       = (const float*)d_in[7];
    const float* Wa       = (const float*)d_in[8];
    // d_in[9] = ba : additive constant inside softmax -> no-op
    const float* Wr       = (const float*)d_in[10];
    const float* br       = (const float*)d_in[11];
    const float* Wo       = (const float*)d_in[12];
    const float* bo       = (const float*)d_in[13];
    float* out = (float*)d_out;

    float *p_mv, *p_mu, *p_er, *p_sw, *p_s, *p_s2, *p_rmT;
    cudaGetSymbolAddress((void**)&p_mv,  g_mv);
    cudaGetSymbolAddress((void**)&p_mu,  g_mu);
    cudaGetSymbolAddress((void**)&p_er,  g_er);
    cudaGetSymbolAddress((void**)&p_sw,  g_sw);
    cudaGetSymbolAddress((void**)&p_s,   g_s);
    cudaGetSymbolAddress((void**)&p_s2,  g_s2);
    cudaGetSymbolAddress((void**)&p_rmT, g_rmT);

    const int BIG = 1 << 30;

    // 1. transpose RM -> rmT [512, 1024]
    { dim3 g(RMSv / 32, Rv / 32), b(32, 8); transpose_rm_kernel<<<g, b>>>(RM); }

    // 2. per-mention projections (fused): mv = mention@Wv^T, mu = mention@Wu^T
    //    [2048, 256], K=1024; grid x: blocks 0-1 -> Wv, 2-3 -> Wu
    { dim3 g(2 * (Av / 128), NMENT / 64);   // (4, 32)
      gemm_bf16x3_nt<<<g, 256>>>(Hv, mention, Hv, Wv, Wu, Av / 128, Hv,
                                 p_mv, p_mu, Av, nullptr, 0); }

    // 3. per-mention gate logit [2048]
    gate_kernel<<<NMENT / 8, 256>>>(bv, bu, Wa);

    // 4. softmax over K + pool -> entity_reprs [1024, 1024]
    softmax_pool_kernel<<<NBE, 256>>>(mention, entities, masks);

    // 5. sw = RM @ Wr^T + br   [1024(R), 1024(H)], K=512
    { dim3 g(Hv / 128, Rv / 64);
      gemm_bf16x3_nt<<<g, 256>>>(RMSv, RM, RMSv, Wr, Wr, BIG, RMSv,
                                 p_sw, p_sw, Hv, br, 0); }

    // 6. s = ER @ sw^T   [1024, 1024], K=1024
    { dim3 g(Rv / 128, NBE / 64);
      gemm_bf16x3_nt<<<g, 256>>>(Hv, p_er, Hv, p_sw, p_sw, BIG, Hv,
                                 p_s, p_s, Rv, nullptr, 0); }

    // 7. s2 = s @ rmT^T   [1024, 512], K=1024
    { dim3 g(RMSv / 128, NBE / 64);
      gemm_bf16x3_nt<<<g, 256>>>(Rv, p_s, Rv, p_rmT, p_rmT, BIG, Rv,
                                 p_s2, p_s2, RMSv, nullptr, 0); }

    // 8. out = ER @ Wo[:, :H]^T   [1024, 1024], K=1024 (ldb = H+RMS)
    { dim3 g(Hv / 128, NBE / 64);
      gemm_bf16x3_nt<<<g, 256>>>(Hv, p_er, Hv, Wo, Wo, BIG, Hv + RMSv,
                                 out, out, Hv, nullptr, 0); }

    // 9. out += s2 @ Wo[:, H:]^T + bo   K=512
    { dim3 g(Hv / 128, NBE / 64);
      gemm_bf16x3_nt<<<g, 256>>>(RMSv, p_s2, RMSv, Wo + Hv, Wo + Hv, BIG, Hv + RMSv,
                                 out, out, Hv, bo, 1); }
}